// round 2
// baseline (speedup 1.0000x reference)
#include <cuda_runtime.h>
#include <math.h>

// ---------------------------------------------------------------------------
// EquiConv fused kernel, v1 (FFMA fp32 baseline)
//
// Pipeline:
//   k1_prep : H[e,j]   = 1.679*silu((fw@W1)/8)/8      (E x 64, /8 folds W2 scale)
//             g_C[e,u] : u<32 : pw00 * x2_0 * x1_0[u]          (seg0 coef)
//                        u>=32: pw110/sqrt(3) * sum_i x1_1*x2_1 (seg1 coef)
//   k2_main : per 128-row CTA: stream W2 in 64-col chunks, GEMM tile in regs,
//             stage chunk in SMEM, contract into out0/s/q register accums,
//             epilogue writes out[e, 80].
// ---------------------------------------------------------------------------

#define E_ROWS   65536
#define KD       64
#define NCOL     2304
#define TILE_R   128
#define NC       64
#define HS_STRIDE 132   // 128 + 4 (keeps float4 alignment, breaks bank stride)
#define WB_STRIDE 68    // 64 + 4

// scratch (device globals: allocation-free rule)
__device__ float g_H[E_ROWS * KD];      // 16.8 MB
__device__ float g_C[E_ROWS * 48];      // 12.6 MB

// ---------------------------------------------------------------------------
__global__ void k1_prep(const float* __restrict__ fea_in1,
                        const float* __restrict__ fea_in2,
                        const float* __restrict__ fea_weight,
                        const float* __restrict__ W1)
{
    __shared__ float W1s[64 * 64];
    __shared__ float fws[32 * 64];

    const int t  = threadIdx.x;
    const int r0 = blockIdx.x * 32;

    for (int idx = t; idx < 64 * 64; idx += 256) W1s[idx] = W1[idx];
    for (int idx = t; idx < 32 * 64; idx += 256) fws[idx] = fea_weight[r0 * 64 + idx];
    __syncthreads();

    const int rl   = t >> 3;   // local row 0..31
    const int l8   = t & 7;    // 0..7 -> owns j = jj*8 + l8
    const int grow = r0 + rl;

    float acc[8];
#pragma unroll
    for (int jj = 0; jj < 8; jj++) acc[jj] = 0.f;

#pragma unroll 8
    for (int k = 0; k < 64; k++) {
        const float fv = fws[rl * 64 + k];
#pragma unroll
        for (int jj = 0; jj < 8; jj++)
            acc[jj] += fv * W1s[k * 64 + jj * 8 + l8];
    }

#pragma unroll
    for (int jj = 0; jj < 8; jj++) {
        const float z = acc[jj] * 0.125f;               // / sqrt(64)
        const float s = z / (1.f + expf(-z));           // silu
        g_H[grow * 64 + jj * 8 + l8] = 1.679f * s * 0.125f;  // fold W2's /8
    }

    // contraction coefficients for segments 0/1
    const float x20  = fea_in2[grow * 4 + 0];
    const float x21a = fea_in2[grow * 4 + 1];
    const float x21b = fea_in2[grow * 4 + 2];
    const float x21c = fea_in2[grow * 4 + 3];

    for (int u = l8; u < 32; u += 8)
        g_C[grow * 48 + u] = 0.125f * x20 * fea_in1[grow * 80 + u];   // pw00=1/8

    for (int u = l8; u < 16; u += 8) {
        const float* p = fea_in1 + grow * 80 + 32 + u * 3;
        const float b  = p[0] * x21a + p[1] * x21b + p[2] * x21c;
        g_C[grow * 48 + 32 + u] = 0.10206207261596575f * b;           // 1/sqrt(96)
    }
}

// ---------------------------------------------------------------------------
__global__ __launch_bounds__(256, 2)
void k2_main(const float* __restrict__ fea_in1,
             const float* __restrict__ fea_in2,
             const float* __restrict__ W2,
             float* __restrict__ out)
{
    extern __shared__ float sm[];
    float* Hs   = sm;                        // 64 * 132      = 8448
    float* W2s  = Hs   + 64 * HS_STRIDE;     // 64 * 64       = 4096
    float* wbuf = W2s  + 64 * NC;            // 128 * 68      = 8704
    float* Cs   = wbuf + TILE_R * WB_STRIDE; // 128 * 48      = 6144
    // total 27392 floats = 109568 bytes

    const int tid = threadIdx.x;
    const int tx  = tid & 15;   // column group
    const int ty  = tid >> 4;   // row group (owns rows ty*8 .. ty*8+7)
    const int r0  = blockIdx.x * TILE_R;

    // Load H tile transposed: Hs[j][row]
    for (int idx = tid; idx < TILE_R * 64; idx += 256) {
        const int row = idx >> 6;
        const int j   = idx & 63;
        Hs[j * HS_STRIDE + row] = g_H[(r0 + row) * 64 + j];
    }

    // persistent per-thread output accumulators
    float o0[8][2];
    float sA[8];
    float qA[8][3];
#pragma unroll
    for (int r = 0; r < 8; r++) {
        o0[r][0] = 0.f; o0[r][1] = 0.f;
        sA[r] = 0.f;
        qA[r][0] = 0.f; qA[r][1] = 0.f; qA[r][2] = 0.f;
    }

    for (int m = 0; m < 36; m++) {
        __syncthreads();   // prev contraction done before overwriting W2s/Cs

        // ---- load W2 chunk (64 x 64), coalesced over columns ----
        const int c0 = m * NC;
        for (int idx = tid; idx < 64 * NC; idx += 256) {
            const int j = idx >> 6;
            const int c = idx & 63;
            W2s[idx] = W2[j * NCOL + c0 + c];
        }
        // ---- (re)load coefficient section at segment boundaries ----
        if (m == 0) {
            for (int idx = tid; idx < TILE_R * 48; idx += 256)
                Cs[idx] = g_C[r0 * 48 + idx];
        } else if (m == 24) {            // seg2 coefs: x1_0[u], u<32
            for (int idx = tid; idx < TILE_R * 32; idx += 256) {
                const int row = idx >> 5;
                const int i   = idx & 31;
                Cs[row * 48 + i] = fea_in1[(r0 + row) * 80 + i];
            }
        } else if (m == 32) {            // seg3 coefs: x1_1[u,k] flat (48)
            for (int idx = tid; idx < TILE_R * 48; idx += 256) {
                const int row = idx / 48;
                const int i   = idx - row * 48;
                Cs[row * 48 + i] = fea_in1[(r0 + row) * 80 + 32 + i];
            }
        }
        __syncthreads();

        // ---- GEMM: 8 rows x 4 cols register tile, K = 64 ----
        float acc[8][4];
#pragma unroll
        for (int r = 0; r < 8; r++) {
            acc[r][0] = 0.f; acc[r][1] = 0.f; acc[r][2] = 0.f; acc[r][3] = 0.f;
        }
        const float* wp = W2s + tx * 4;
        const float* hp = Hs  + ty * 8;
#pragma unroll 4
        for (int j = 0; j < 64; j++) {
            const float4 w4 = *(const float4*)(wp + j * NC);
            const float4 ha = *(const float4*)(hp + j * HS_STRIDE);
            const float4 hb = *(const float4*)(hp + j * HS_STRIDE + 4);
            const float hv[8] = {ha.x, ha.y, ha.z, ha.w, hb.x, hb.y, hb.z, hb.w};
#pragma unroll
            for (int r = 0; r < 8; r++) {
                acc[r][0] += hv[r] * w4.x;
                acc[r][1] += hv[r] * w4.y;
                acc[r][2] += hv[r] * w4.z;
                acc[r][3] += hv[r] * w4.w;
            }
        }
        // stage chunk of w in SMEM
#pragma unroll
        for (int r = 0; r < 8; r++) {
            float4 v = make_float4(acc[r][0], acc[r][1], acc[r][2], acc[r][3]);
            *(float4*)(wbuf + (ty * 8 + r) * WB_STRIDE + tx * 4) = v;
        }
        __syncthreads();

        // ---- contraction of this chunk ----
        if (m < 24) {
            // seg0/1: cols = u*32 + wo, u in {2m, 2m+1}; thread owns wo = 2tx, 2tx+1
            const int u0 = m * 2;
#pragma unroll
            for (int r = 0; r < 8; r++) {
                const int row = ty * 8 + r;
                const float* wb = wbuf + row * WB_STRIDE;
                const float cA = Cs[row * 48 + u0];
                const float cB = Cs[row * 48 + u0 + 1];
                o0[r][0] += cA * wb[tx * 2]     + cB * wb[32 + tx * 2];
                o0[r][1] += cA * wb[tx * 2 + 1] + cB * wb[32 + tx * 2 + 1];
            }
        } else if (m < 32) {
            // seg2: cols = u*16 + wo, 4 u per chunk; thread owns wo = tx
            const int u0 = (m - 24) * 4;
#pragma unroll
            for (int r = 0; r < 8; r++) {
                const int row = ty * 8 + r;
                const float* wb = wbuf + row * WB_STRIDE;
                float s = 0.f;
#pragma unroll
                for (int uu = 0; uu < 4; uu++)
                    s += Cs[row * 48 + u0 + uu] * wb[uu * 16 + tx];
                sA[r] += s;
            }
        } else {
            // seg3: cols = u*16 + wo; coef x1_1[u,k]; thread owns wo = tx, k=0..2
            const int u0 = (m - 32) * 4;
#pragma unroll
            for (int r = 0; r < 8; r++) {
                const int row = ty * 8 + r;
                const float* wb = wbuf + row * WB_STRIDE;
#pragma unroll
                for (int uu = 0; uu < 4; uu++) {
                    const float wv = wb[uu * 16 + tx];
                    const float* cp = Cs + row * 48 + (u0 + uu) * 3;
                    qA[r][0] += cp[0] * wv;
                    qA[r][1] += cp[1] * wv;
                    qA[r][2] += cp[2] * wv;
                }
            }
        }
    }

    // ---- epilogue ----
    const float c011 = 0.125f;                 // pw011 / sqrt(3) = 1/8
    const float c101 = 0.17677669529663687f;   // pw101 / sqrt(3) = 1/sqrt(32)
#pragma unroll
    for (int r = 0; r < 8; r++) {
        const int g = r0 + ty * 8 + r;
        float* orow = out + g * 80;
        orow[tx * 2]     = o0[r][0];
        orow[tx * 2 + 1] = o0[r][1];
        const float x20 = fea_in2[g * 4 + 0];
        const float s   = sA[r];
#pragma unroll
        for (int k = 0; k < 3; k++) {
            const float x21 = fea_in2[g * 4 + 1 + k];
            orow[32 + tx * 3 + k] = c011 * x21 * s + c101 * x20 * qA[r][k];
        }
    }
}

// ---------------------------------------------------------------------------
extern "C" void kernel_launch(void* const* d_in, const int* in_sizes, int n_in,
                              void* d_out, int out_size)
{
    const float* fea_in1    = (const float*)d_in[0];
    const float* fea_in2    = (const float*)d_in[1];
    const float* fea_weight = (const float*)d_in[2];
    const float* W1         = (const float*)d_in[3];
    const float* W2         = (const float*)d_in[4];
    float* out = (float*)d_out;

    const int smem_bytes = (64 * HS_STRIDE + 64 * NC + TILE_R * WB_STRIDE + TILE_R * 48) * 4;
    cudaFuncSetAttribute(k2_main, cudaFuncAttributeMaxDynamicSharedMemorySize, smem_bytes);

    k1_prep<<<E_ROWS / 32, 256>>>(fea_in1, fea_in2, fea_weight, W1);
    k2_main<<<E_ROWS / TILE_R, 256, smem_bytes>>>(fea_in1, fea_in2, W2, out);
}

// round 4
// speedup vs baseline: 2.2458x; 2.2458x over previous
#include <cuda_runtime.h>
#include <cuda_bf16.h>
#include <math.h>
#include <stdint.h>

// ---------------------------------------------------------------------------
// EquiConv v3: HMMA (mma.sync bf16) fused GEMM+contraction — base sm_103 ISA.
//   k0_prepB : W2 -> g_B  [36 chunks][64 n][192 k] bf16, K-blocks [Bh|Bh|Bl]
//   k1_prep  : H = 1.679*silu((fw@W1)/8)/8 -> g_H ; seg0/1 coefs -> g_C
//   k2_main  : 128-row CTA, 4 warps (32 rows each). A=[Ah|Al|Ah] in SMEM.
//              36 chunks of 64 cols: cp.async double-buffered B, per-warp
//              m16n8k16 HMMA (12 k-steps x 16 tiles), fragment-local
//              contraction into persistent out0/s/q registers.
// ---------------------------------------------------------------------------

#define E_ROWS 65536
#define TILE_R 128
#define NCHUNK 36
#define CH_N   64
#define KTOT   192
#define ASTR   200           // bf16 elems per A row (192 + 8 pad)
#define BSTR   200
#define BS_OFF (128*ASTR*2)  // 51200 bytes
#define BBUF_B (CH_N*BSTR*2) // 25600 bytes per buffer
#define SMEM_TOTAL (BS_OFF + 2*BBUF_B)  // 102400

__device__ float g_H[E_ROWS * 64];
__device__ float g_C[E_ROWS * 48];
__device__ __align__(16) __nv_bfloat16 g_B[NCHUNK * CH_N * KTOT];

// ------------------------------ asm helpers --------------------------------
__device__ __forceinline__ uint32_t smem_u32(const void* p) {
    uint32_t a;
    asm("{ .reg .u64 t; cvta.to.shared.u64 t, %1; cvt.u32.u64 %0, t; }" : "=r"(a) : "l"(p));
    return a;
}
#define LDSM4(r, a)                                                          \
    asm volatile("ldmatrix.sync.aligned.m8n8.x4.shared.b16 {%0,%1,%2,%3},[%4];" \
                 : "=r"((r)[0]), "=r"((r)[1]), "=r"((r)[2]), "=r"((r)[3]) : "r"(a))
#define MMA16816(d, a, b)                                                    \
    asm volatile("mma.sync.aligned.m16n8k16.row.col.f32.bf16.bf16.f32 "      \
                 "{%0,%1,%2,%3},{%4,%5,%6,%7},{%8,%9},{%0,%1,%2,%3};"        \
                 : "+f"((d)[0]), "+f"((d)[1]), "+f"((d)[2]), "+f"((d)[3])    \
                 : "r"((a)[0]), "r"((a)[1]), "r"((a)[2]), "r"((a)[3]),       \
                   "r"((b)[0]), "r"((b)[1]))
#define CP_ASYNC16(d, s) \
    asm volatile("cp.async.cg.shared.global [%0], [%1], 16;" :: "r"(d), "l"(s))
#define CP_COMMIT()   asm volatile("cp.async.commit_group;" ::: "memory")
#define CP_WAIT1()    asm volatile("cp.async.wait_group 1;" ::: "memory")
#define CP_WAIT0()    asm volatile("cp.async.wait_group 0;" ::: "memory")

// stage one B chunk (64 rows x 384B) into smem rows of stride 400B
__device__ __forceinline__ void stage_B(int chunk, uint32_t dst, int tid) {
    const char* src = (const char*)(g_B + chunk * CH_N * KTOT);
    for (int t16 = tid; t16 < 1536; t16 += 128) {
        int row = t16 / 24, c = t16 - row * 24;
        CP_ASYNC16(dst + row * 400 + c * 16, src + row * 384 + c * 16);
    }
}

// ---------------------------------------------------------------------------
__global__ void k0_prepB(const float* __restrict__ W2) {
    int id = blockIdx.x * 256 + threadIdx.x;
    if (id >= 2304 * 64) return;
    int col = id >> 6, kk = id & 63;
    int chunk = col >> 6, n = col & 63;
    float w = W2[kk * 2304 + col];
    __nv_bfloat16 hi = __float2bfloat16(w);
    __nv_bfloat16 lo = __float2bfloat16(w - __bfloat162float(hi));
    __nv_bfloat16* base = g_B + (chunk * CH_N + n) * KTOT;
    base[kk]        = hi;   // pairs with Ah
    base[64 + kk]   = hi;   // pairs with Al
    base[128 + kk]  = lo;   // pairs with Ah
}

// ---------------------------------------------------------------------------
__global__ void k1_prep(const float* __restrict__ fea_in1,
                        const float* __restrict__ fea_in2,
                        const float* __restrict__ fea_weight,
                        const float* __restrict__ W1)
{
    __shared__ float W1s[64 * 64];
    __shared__ float fws[32 * 64];
    const int t  = threadIdx.x;
    const int r0 = blockIdx.x * 32;

    for (int idx = t; idx < 64 * 64; idx += 256) W1s[idx] = W1[idx];
    for (int idx = t; idx < 32 * 64; idx += 256) fws[idx] = fea_weight[r0 * 64 + idx];
    __syncthreads();

    const int rl = t >> 3, l8 = t & 7, grow = r0 + rl;
    float acc[8];
#pragma unroll
    for (int jj = 0; jj < 8; jj++) acc[jj] = 0.f;
#pragma unroll 8
    for (int k = 0; k < 64; k++) {
        const float fv = fws[rl * 64 + k];
#pragma unroll
        for (int jj = 0; jj < 8; jj++) acc[jj] += fv * W1s[k * 64 + jj * 8 + l8];
    }
#pragma unroll
    for (int jj = 0; jj < 8; jj++) {
        const float z = acc[jj] * 0.125f;
        const float s = z / (1.f + expf(-z));
        g_H[grow * 64 + jj * 8 + l8] = 1.679f * s * 0.125f;   // fold W2's /8
    }

    const float x20  = fea_in2[grow * 4 + 0];
    const float x21a = fea_in2[grow * 4 + 1];
    const float x21b = fea_in2[grow * 4 + 2];
    const float x21c = fea_in2[grow * 4 + 3];
    for (int u = l8; u < 32; u += 8)
        g_C[grow * 48 + u] = 0.125f * x20 * fea_in1[grow * 80 + u];      // pw00
    for (int u = l8; u < 16; u += 8) {
        const float* p = fea_in1 + grow * 80 + 32 + u * 3;
        const float b = p[0] * x21a + p[1] * x21b + p[2] * x21c;
        g_C[grow * 48 + 32 + u] = 0.10206207261596575f * b;              // 1/sqrt(96)
    }
}

// ---------------------------------------------------------------------------
__global__ __launch_bounds__(128, 2)
void k2_main(const float* __restrict__ fea_in1,
             const float* __restrict__ fea_in2,
             float* __restrict__ out)
{
    extern __shared__ __align__(16) char smem[];
    const uint32_t sbase = smem_u32(smem);
    const int tid = threadIdx.x, wid = tid >> 5, lane = tid & 31;
    const int r0 = blockIdx.x * TILE_R;

    // ---- build A tile: [128 rows][192 k] bf16 = [Ah|Al|Ah], stride 200 ----
    __nv_bfloat16* As = (__nv_bfloat16*)smem;
    for (int idx = tid; idx < 128 * 64; idx += 128) {
        const int r = idx >> 6, j = idx & 63;
        const float h = g_H[(r0 + r) * 64 + j];
        const __nv_bfloat16 hi = __float2bfloat16(h);
        const __nv_bfloat16 lo = __float2bfloat16(h - __bfloat162float(hi));
        As[r * ASTR + j]        = hi;
        As[r * ASTR + 64 + j]   = lo;
        As[r * ASTR + 128 + j]  = hi;
    }
    // ---- prefetch B chunks 0,1 ----
    stage_B(0, sbase + BS_OFF, tid);            CP_COMMIT();
    stage_B(1, sbase + BS_OFF + BBUF_B, tid);   CP_COMMIT();
    __syncthreads();

    // ldmatrix address groups
    const int gp = lane >> 3, lr = lane & 7;
    uint32_t aBase[2];
#pragma unroll
    for (int mt = 0; mt < 2; mt++)
        aBase[mt] = sbase + (uint32_t)(((wid * 32 + mt * 16 + 8 * (gp & 1) + lr) * ASTR
                                        + 8 * (gp >> 1)) * 2);
    uint32_t bOff[4];
#pragma unroll
    for (int p = 0; p < 4; p++)
        bOff[p] = (uint32_t)(((16 * p + 8 * (gp >> 1) + lr) * BSTR + 8 * (gp & 1)) * 2);

    // persistent per-thread output accumulators
    float o0[32], sA[16], qA[48];
#pragma unroll
    for (int i = 0; i < 32; i++) o0[i] = 0.f;
#pragma unroll
    for (int i = 0; i < 16; i++) sA[i] = 0.f;
#pragma unroll
    for (int i = 0; i < 48; i++) qA[i] = 0.f;

    const int rowq = lane >> 2;               // 0..7
    const int rbase = r0 + wid * 32 + rowq;   // + mt*16 + rh*8
    const int q2 = (lane & 3) * 2;

#pragma unroll 1
    for (int m = 0; m < NCHUNK; m++) {
        if (m < NCHUNK - 1) { CP_WAIT1(); } else { CP_WAIT0(); }
        __syncthreads();

        const uint32_t sbB = sbase + BS_OFF + (uint32_t)(m & 1) * BBUF_B;

        float acc[2][8][4];
#pragma unroll
        for (int mt = 0; mt < 2; mt++)
#pragma unroll
            for (int j = 0; j < 8; j++)
#pragma unroll
                for (int c = 0; c < 4; c++) acc[mt][j][c] = 0.f;

#pragma unroll
        for (int ks = 0; ks < 12; ks++) {
            uint32_t a[2][4];
            LDSM4(a[0], aBase[0] + ks * 32);
            LDSM4(a[1], aBase[1] + ks * 32);
            uint32_t b[8][2];
#pragma unroll
            for (int p = 0; p < 4; p++) {
                uint32_t r[4];
                LDSM4(r, sbB + bOff[p] + ks * 32);
                b[2 * p][0] = r[0]; b[2 * p][1] = r[1];
                b[2 * p + 1][0] = r[2]; b[2 * p + 1][1] = r[3];
            }
#pragma unroll
            for (int mt = 0; mt < 2; mt++)
#pragma unroll
                for (int j = 0; j < 8; j++)
                    MMA16816(acc[mt][j], a[mt], b[j]);
        }

        // ---- fragment-local contraction ----
        if (m < 24) {
            const int uoff = (m < 16) ? (2 * m) : (32 + 2 * (m - 16));
#pragma unroll
            for (int mt = 0; mt < 2; mt++)
#pragma unroll
                for (int rh = 0; rh < 2; rh++) {
                    const int row = rbase + mt * 16 + rh * 8;
                    const float c0v = g_C[row * 48 + uoff];
                    const float c1v = g_C[row * 48 + uoff + 1];
#pragma unroll
                    for (int j = 0; j < 8; j++) {
                        const float c = (j < 4) ? c0v : c1v;
                        const int s = ((mt * 2 + rh) * 4 + (j & 3)) * 2;
                        o0[s]     = fmaf(c, acc[mt][j][rh * 2],     o0[s]);
                        o0[s + 1] = fmaf(c, acc[mt][j][rh * 2 + 1], o0[s + 1]);
                    }
                }
        } else if (m < 32) {
            const int u0 = 4 * (m - 24);
#pragma unroll
            for (int mt = 0; mt < 2; mt++)
#pragma unroll
                for (int rh = 0; rh < 2; rh++) {
                    const int row = rbase + mt * 16 + rh * 8;
                    const float* xr = fea_in1 + row * 80 + u0;
                    const int s = (mt * 2 + rh) * 4;
#pragma unroll
                    for (int jh = 0; jh < 4; jh++) {
                        const float c = xr[jh];
                        sA[s]     = fmaf(c, acc[mt][2 * jh][rh * 2],         sA[s]);
                        sA[s + 1] = fmaf(c, acc[mt][2 * jh][rh * 2 + 1],     sA[s + 1]);
                        sA[s + 2] = fmaf(c, acc[mt][2 * jh + 1][rh * 2],     sA[s + 2]);
                        sA[s + 3] = fmaf(c, acc[mt][2 * jh + 1][rh * 2 + 1], sA[s + 3]);
                    }
                }
        } else {
            const int u0 = 4 * (m - 32);
#pragma unroll
            for (int mt = 0; mt < 2; mt++)
#pragma unroll
                for (int rh = 0; rh < 2; rh++) {
                    const int row = rbase + mt * 16 + rh * 8;
                    const float* xr = fea_in1 + row * 80 + 32 + 3 * u0;
                    const int s = (mt * 2 + rh) * 4;
#pragma unroll
                    for (int jh = 0; jh < 4; jh++) {
#pragma unroll
                        for (int k = 0; k < 3; k++) {
                            const float c = xr[3 * jh + k];
                            qA[(s + 0) * 3 + k] = fmaf(c, acc[mt][2 * jh][rh * 2],         qA[(s + 0) * 3 + k]);
                            qA[(s + 1) * 3 + k] = fmaf(c, acc[mt][2 * jh][rh * 2 + 1],     qA[(s + 1) * 3 + k]);
                            qA[(s + 2) * 3 + k] = fmaf(c, acc[mt][2 * jh + 1][rh * 2],     qA[(s + 2) * 3 + k]);
                            qA[(s + 3) * 3 + k] = fmaf(c, acc[mt][2 * jh + 1][rh * 2 + 1], qA[(s + 3) * 3 + k]);
                        }
                    }
                }
        }
        __syncthreads();
        if (m + 2 < NCHUNK) {
            stage_B(m + 2, sbase + BS_OFF + (uint32_t)(m & 1) * BBUF_B, tid);
            CP_COMMIT();
        }
    }

    // ---- epilogue ----
    const float c011 = 0.125f;                 // pw011/sqrt(3)
    const float c101 = 0.17677669529663687f;   // pw101/sqrt(3)
#pragma unroll
    for (int mt = 0; mt < 2; mt++)
#pragma unroll
        for (int rh = 0; rh < 2; rh++) {
            const int row = rbase + mt * 16 + rh * 8;
            float* orow = out + row * 80;
            const int s = (mt * 2 + rh) * 4;
#pragma unroll
            for (int jm = 0; jm < 4; jm++) {
                orow[8 * jm + q2]     = o0[(s + jm) * 2];
                orow[8 * jm + q2 + 1] = o0[(s + jm) * 2 + 1];
            }
            const float x20 = fea_in2[row * 4 + 0];
            const float x21a = fea_in2[row * 4 + 1];
            const float x21b = fea_in2[row * 4 + 2];
            const float x21c = fea_in2[row * 4 + 3];
#pragma unroll
            for (int slot = 0; slot < 4; slot++) {
                const int w = 8 * (slot >> 1) + q2 + (slot & 1);
                const float sv = sA[s + slot];
                orow[32 + 3 * w + 0] = c011 * x21a * sv + c101 * x20 * qA[(s + slot) * 3 + 0];
                orow[32 + 3 * w + 1] = c011 * x21b * sv + c101 * x20 * qA[(s + slot) * 3 + 1];
                orow[32 + 3 * w + 2] = c011 * x21c * sv + c101 * x20 * qA[(s + slot) * 3 + 2];
            }
        }
}

// ---------------------------------------------------------------------------
extern "C" void kernel_launch(void* const* d_in, const int* in_sizes, int n_in,
                              void* d_out, int out_size)
{
    const float* fea_in1    = (const float*)d_in[0];
    const float* fea_in2    = (const float*)d_in[1];
    const float* fea_weight = (const float*)d_in[2];
    const float* W1         = (const float*)d_in[3];
    const float* W2         = (const float*)d_in[4];
    float* out = (float*)d_out;

    cudaFuncSetAttribute(k2_main, cudaFuncAttributeMaxDynamicSharedMemorySize, SMEM_TOTAL);

    k0_prepB<<<576, 256>>>(W2);
    k1_prep<<<E_ROWS / 32, 256>>>(fea_in1, fea_in2, fea_weight, W1);
    k2_main<<<E_ROWS / TILE_R, 128, SMEM_TOTAL>>>(fea_in1, fea_in2, out);
}

// round 5
// speedup vs baseline: 2.5911x; 1.1537x over previous
#include <cuda_runtime.h>
#include <cuda_fp16.h>
#include <math.h>
#include <stdint.h>

// ---------------------------------------------------------------------------
// EquiConv v4: fp16 2-term compensated HMMA, shared-B k-blocks, 2D warp grid.
//   k0_prepB : W2 -> g_B [18 chunks][128 n][64 k] fp16 (Bh)
//   k1_prep  : H = 1.679*silu((fw@W1)/8)/8 -> g_H ; seg0/1 coefs -> g_C
//   k2_main  : 128-row CTA, 256 thr, warps = (rg 0..3) x (cg 0..1).
//              A=[Ah|Al] fp16 (K=128) in SMEM; 18 chunks of 128 cols:
//              cp.async double-buffered B (K=64, reused by Ah and Al blocks),
//              fragment-local contraction, final cg-reduction in SMEM.
// ---------------------------------------------------------------------------

#define E_ROWS 65536
#define TILE_R 128
#define NCHUNK 18
#define ASTR   136                  // fp16 elems per A row (128 + 8)
#define BSTR   72                   // fp16 elems per B row (64 + 8)
#define A_BYTES (128*ASTR*2)        // 34816
#define BS_OFF  A_BYTES
#define BBUF_B  (128*BSTR*2)        // 18432
#define SMEM_TOTAL (A_BYTES + 2*BBUF_B)   // 71680

__device__ float g_H[E_ROWS * 64];
__device__ float g_C[E_ROWS * 48];
__device__ __align__(16) __half g_B[NCHUNK * 128 * 64];

// ------------------------------ asm helpers --------------------------------
__device__ __forceinline__ uint32_t smem_u32(const void* p) {
    uint32_t a;
    asm("{ .reg .u64 t; cvta.to.shared.u64 t, %1; cvt.u32.u64 %0, t; }" : "=r"(a) : "l"(p));
    return a;
}
#define LDSM4(r, a)                                                          \
    asm volatile("ldmatrix.sync.aligned.m8n8.x4.shared.b16 {%0,%1,%2,%3},[%4];" \
                 : "=r"((r)[0]), "=r"((r)[1]), "=r"((r)[2]), "=r"((r)[3]) : "r"(a))
#define MMA16816(d, a, b)                                                    \
    asm volatile("mma.sync.aligned.m16n8k16.row.col.f32.f16.f16.f32 "        \
                 "{%0,%1,%2,%3},{%4,%5,%6,%7},{%8,%9},{%0,%1,%2,%3};"        \
                 : "+f"((d)[0]), "+f"((d)[1]), "+f"((d)[2]), "+f"((d)[3])    \
                 : "r"((a)[0]), "r"((a)[1]), "r"((a)[2]), "r"((a)[3]),       \
                   "r"((b)[0]), "r"((b)[1]))
#define CP_ASYNC16(d, s) \
    asm volatile("cp.async.cg.shared.global [%0], [%1], 16;" :: "r"(d), "l"(s))
#define CP_COMMIT()   asm volatile("cp.async.commit_group;" ::: "memory")
#define CP_WAIT1()    asm volatile("cp.async.wait_group 1;" ::: "memory")
#define CP_WAIT0()    asm volatile("cp.async.wait_group 0;" ::: "memory")

// stage one B chunk (128 n-rows x 128B) into smem rows of stride 144B
__device__ __forceinline__ void stage_B(int chunk, uint32_t dst, int tid) {
    const char* src = (const char*)(g_B + chunk * 128 * 64);
#pragma unroll
    for (int it = 0; it < 4; it++) {
        int t16 = tid + it * 256;
        int row = t16 >> 3, c = t16 & 7;
        CP_ASYNC16(dst + row * 144 + c * 16, src + row * 128 + c * 16);
    }
}

// ---------------------------------------------------------------------------
__global__ void k0_prepB(const float* __restrict__ W2) {
    int id = blockIdx.x * 256 + threadIdx.x;
    if (id >= 2304 * 64) return;
    int col = id >> 6, kk = id & 63;
    int chunk = col >> 7, n = col & 127;
    g_B[(chunk * 128 + n) * 64 + kk] = __float2half(W2[kk * 2304 + col]);
}

// ---------------------------------------------------------------------------
__global__ void k1_prep(const float* __restrict__ fea_in1,
                        const float* __restrict__ fea_in2,
                        const float* __restrict__ fea_weight,
                        const float* __restrict__ W1)
{
    __shared__ float W1s[64 * 64];
    __shared__ float fws[32 * 64];
    const int t  = threadIdx.x;
    const int r0 = blockIdx.x * 32;

    for (int idx = t; idx < 64 * 64; idx += 256) W1s[idx] = W1[idx];
    for (int idx = t; idx < 32 * 64; idx += 256) fws[idx] = fea_weight[r0 * 64 + idx];
    __syncthreads();

    const int rl = t >> 3, l8 = t & 7, grow = r0 + rl;
    float acc[8];
#pragma unroll
    for (int jj = 0; jj < 8; jj++) acc[jj] = 0.f;
#pragma unroll 8
    for (int k = 0; k < 64; k++) {
        const float fv = fws[rl * 64 + k];
#pragma unroll
        for (int jj = 0; jj < 8; jj++) acc[jj] += fv * W1s[k * 64 + jj * 8 + l8];
    }
#pragma unroll
    for (int jj = 0; jj < 8; jj++) {
        const float z = acc[jj] * 0.125f;
        const float s = z / (1.f + expf(-z));
        g_H[grow * 64 + jj * 8 + l8] = 1.679f * s * 0.125f;   // fold W2's /8
    }

    const float x20  = fea_in2[grow * 4 + 0];
    const float x21a = fea_in2[grow * 4 + 1];
    const float x21b = fea_in2[grow * 4 + 2];
    const float x21c = fea_in2[grow * 4 + 3];
    for (int u = l8; u < 32; u += 8)
        g_C[grow * 48 + u] = 0.125f * x20 * fea_in1[grow * 80 + u];      // pw00
    for (int u = l8; u < 16; u += 8) {
        const float* p = fea_in1 + grow * 80 + 32 + u * 3;
        const float b = p[0] * x21a + p[1] * x21b + p[2] * x21c;
        g_C[grow * 48 + 32 + u] = 0.10206207261596575f * b;              // 1/sqrt(96)
    }
}

// ---------------------------------------------------------------------------
__global__ __launch_bounds__(256, 1)
void k2_main(const float* __restrict__ fea_in1,
             const float* __restrict__ fea_in2,
             float* __restrict__ out)
{
    extern __shared__ __align__(16) char smem[];
    const uint32_t sbase = smem_u32(smem);
    const int tid = threadIdx.x, wid = tid >> 5, lane = tid & 31;
    const int rg = wid >> 1, cg = wid & 1;
    const int r0 = blockIdx.x * TILE_R;

    // ---- build A tile: [128 rows][128 k] fp16 = [Ah|Al], stride 136 ----
    __half* As = (__half*)smem;
    for (int idx = tid; idx < 128 * 64; idx += 256) {
        const int r = idx >> 6, j = idx & 63;
        const float h = g_H[(r0 + r) * 64 + j];
        const __half hi = __float2half(h);
        const __half lo = __float2half(h - __half2float(hi));
        As[r * ASTR + j]      = hi;
        As[r * ASTR + 64 + j] = lo;
    }
    stage_B(0, sbase + BS_OFF, tid);            CP_COMMIT();
    stage_B(1, sbase + BS_OFF + BBUF_B, tid);   CP_COMMIT();
    __syncthreads();

    // ldmatrix address groups
    const int gp = lane >> 3, lr = lane & 7;
    uint32_t aBase[2];
#pragma unroll
    for (int mt = 0; mt < 2; mt++)
        aBase[mt] = sbase + (uint32_t)(((rg * 32 + mt * 16 + 8 * (gp & 1) + lr) * ASTR
                                        + 8 * (gp >> 1)) * 2);
    uint32_t bOff[4];
#pragma unroll
    for (int p = 0; p < 4; p++)
        bOff[p] = (uint32_t)(((cg * 64 + 16 * p + 8 * (gp >> 1) + lr) * BSTR
                              + 8 * (gp & 1)) * 2);

    // persistent per-thread partial accumulators
    float o0[32], sA[16], qA[48];
#pragma unroll
    for (int i = 0; i < 32; i++) o0[i] = 0.f;
#pragma unroll
    for (int i = 0; i < 16; i++) sA[i] = 0.f;
#pragma unroll
    for (int i = 0; i < 48; i++) qA[i] = 0.f;

    const int rowq = lane >> 2;
    const int rbase = r0 + rg * 32 + rowq;
    const int q2 = (lane & 3) * 2;

#pragma unroll 1
    for (int m = 0; m < NCHUNK; m++) {
        if (m < NCHUNK - 2) { CP_WAIT1(); } else { CP_WAIT0(); }
        __syncthreads();
        const uint32_t sbB = sbase + BS_OFF + (uint32_t)(m & 1) * BBUF_B;

        float acc[2][8][4];
#pragma unroll
        for (int mt = 0; mt < 2; mt++)
#pragma unroll
            for (int j = 0; j < 8; j++)
#pragma unroll
                for (int c = 0; c < 4; c++) acc[mt][j][c] = 0.f;

#pragma unroll
        for (int ksb = 0; ksb < 4; ksb++) {
            uint32_t b[8][2];
#pragma unroll
            for (int p = 0; p < 4; p++) {
                uint32_t r[4];
                LDSM4(r, sbB + bOff[p] + ksb * 32);
                b[2 * p][0] = r[0]; b[2 * p][1] = r[1];
                b[2 * p + 1][0] = r[2]; b[2 * p + 1][1] = r[3];
            }
            uint32_t a[2][4];
            // Ah block
            LDSM4(a[0], aBase[0] + ksb * 32);
            LDSM4(a[1], aBase[1] + ksb * 32);
#pragma unroll
            for (int mt = 0; mt < 2; mt++)
#pragma unroll
                for (int j = 0; j < 8; j++)
                    MMA16816(acc[mt][j], a[mt], b[j]);
            // Al block (reuses same B fragments)
            LDSM4(a[0], aBase[0] + 128 + ksb * 32);
            LDSM4(a[1], aBase[1] + 128 + ksb * 32);
#pragma unroll
            for (int mt = 0; mt < 2; mt++)
#pragma unroll
                for (int j = 0; j < 8; j++)
                    MMA16816(acc[mt][j], a[mt], b[j]);
        }

        // ---- fragment-local contraction (cg-partial) ----
        if (m < 12) {
            const int ubase = m * 4 + cg * 2;
#pragma unroll
            for (int mt = 0; mt < 2; mt++)
#pragma unroll
                for (int rh = 0; rh < 2; rh++) {
                    const int row = rbase + mt * 16 + rh * 8;
                    const float c0v = g_C[row * 48 + ubase];
                    const float c1v = g_C[row * 48 + ubase + 1];
#pragma unroll
                    for (int j = 0; j < 8; j++) {
                        const float c = (j < 4) ? c0v : c1v;
                        const int s = ((mt * 2 + rh) * 4 + (j & 3)) * 2;
                        o0[s]     = fmaf(c, acc[mt][j][rh * 2],     o0[s]);
                        o0[s + 1] = fmaf(c, acc[mt][j][rh * 2 + 1], o0[s + 1]);
                    }
                }
        } else if (m < 16) {
            const int u0 = (m - 12) * 8 + cg * 4;
#pragma unroll
            for (int mt = 0; mt < 2; mt++)
#pragma unroll
                for (int rh = 0; rh < 2; rh++) {
                    const int row = rbase + mt * 16 + rh * 8;
                    const float* xr = fea_in1 + row * 80 + u0;
                    const int s = (mt * 2 + rh) * 4;
#pragma unroll
                    for (int jh = 0; jh < 4; jh++) {
                        const float cu = xr[jh];
                        sA[s]     = fmaf(cu, acc[mt][2 * jh][rh * 2],         sA[s]);
                        sA[s + 1] = fmaf(cu, acc[mt][2 * jh][rh * 2 + 1],     sA[s + 1]);
                        sA[s + 2] = fmaf(cu, acc[mt][2 * jh + 1][rh * 2],     sA[s + 2]);
                        sA[s + 3] = fmaf(cu, acc[mt][2 * jh + 1][rh * 2 + 1], sA[s + 3]);
                    }
                }
        } else {
            const int u0 = (m - 16) * 8 + cg * 4;
#pragma unroll
            for (int mt = 0; mt < 2; mt++)
#pragma unroll
                for (int rh = 0; rh < 2; rh++) {
                    const int row = rbase + mt * 16 + rh * 8;
                    const float* xr = fea_in1 + row * 80 + 32 + 3 * u0;
                    const int s = (mt * 2 + rh) * 4;
#pragma unroll
                    for (int jh = 0; jh < 4; jh++) {
#pragma unroll
                        for (int k = 0; k < 3; k++) {
                            const float cu = xr[3 * jh + k];
                            qA[(s + 0) * 3 + k] = fmaf(cu, acc[mt][2 * jh][rh * 2],         qA[(s + 0) * 3 + k]);
                            qA[(s + 1) * 3 + k] = fmaf(cu, acc[mt][2 * jh][rh * 2 + 1],     qA[(s + 1) * 3 + k]);
                            qA[(s + 2) * 3 + k] = fmaf(cu, acc[mt][2 * jh + 1][rh * 2],     qA[(s + 2) * 3 + k]);
                            qA[(s + 3) * 3 + k] = fmaf(cu, acc[mt][2 * jh + 1][rh * 2 + 1], qA[(s + 3) * 3 + k]);
                        }
                    }
                }
        }
        __syncthreads();
        if (m + 2 < NCHUNK) {
            stage_B(m + 2, sbase + BS_OFF + (uint32_t)(m & 1) * BBUF_B, tid);
            CP_COMMIT();
        }
    }

    // ---- cross-cg reduction (cg=1 partials -> cg=0) ----
    float* red = (float*)smem;                 // 128 thr * 96 f = 49152 B, fits
    const int half_id = rg * 32 + lane;
    if (cg == 1) {
        float* dst = red + half_id * 96;
#pragma unroll
        for (int i = 0; i < 32; i++) dst[i] = o0[i];
#pragma unroll
        for (int i = 0; i < 16; i++) dst[32 + i] = sA[i];
#pragma unroll
        for (int i = 0; i < 48; i++) dst[48 + i] = qA[i];
    }
    __syncthreads();
    if (cg == 0) {
        const float* src = red + half_id * 96;
#pragma unroll
        for (int i = 0; i < 32; i++) o0[i] += src[i];
#pragma unroll
        for (int i = 0; i < 16; i++) sA[i] += src[32 + i];
#pragma unroll
        for (int i = 0; i < 48; i++) qA[i] += src[48 + i];

        // ---- epilogue ----
        const float c011 = 0.125f;                 // pw011/sqrt(3)
        const float c101 = 0.17677669529663687f;   // pw101/sqrt(3)
#pragma unroll
        for (int mt = 0; mt < 2; mt++)
#pragma unroll
            for (int rh = 0; rh < 2; rh++) {
                const int row = rbase + mt * 16 + rh * 8;
                float* orow = out + row * 80;
                const int s = (mt * 2 + rh) * 4;
#pragma unroll
                for (int jm = 0; jm < 4; jm++) {
                    orow[8 * jm + q2]     = o0[(s + jm) * 2];
                    orow[8 * jm + q2 + 1] = o0[(s + jm) * 2 + 1];
                }
                const float x20  = fea_in2[row * 4 + 0];
                const float x21a = fea_in2[row * 4 + 1];
                const float x21b = fea_in2[row * 4 + 2];
                const float x21c = fea_in2[row * 4 + 3];
#pragma unroll
                for (int slot = 0; slot < 4; slot++) {
                    const int w = 8 * (slot >> 1) + q2 + (slot & 1);
                    const float sv = sA[s + slot];
                    orow[32 + 3 * w + 0] = c011 * x21a * sv + c101 * x20 * qA[(s + slot) * 3 + 0];
                    orow[32 + 3 * w + 1] = c011 * x21b * sv + c101 * x20 * qA[(s + slot) * 3 + 1];
                    orow[32 + 3 * w + 2] = c011 * x21c * sv + c101 * x20 * qA[(s + slot) * 3 + 2];
                }
            }
    }
}

// ---------------------------------------------------------------------------
extern "C" void kernel_launch(void* const* d_in, const int* in_sizes, int n_in,
                              void* d_out, int out_size)
{
    const float* fea_in1    = (const float*)d_in[0];
    const float* fea_in2    = (const float*)d_in[1];
    const float* fea_weight = (const float*)d_in[2];
    const float* W1         = (const float*)d_in[3];
    const float* W2         = (const float*)d_in[4];
    float* out = (float*)d_out;

    cudaFuncSetAttribute(k2_main, cudaFuncAttributeMaxDynamicSharedMemorySize, SMEM_TOTAL);

    k0_prepB<<<576, 256>>>(W2);
    k1_prep<<<E_ROWS / 32, 256>>>(fea_in1, fea_in2, fea_weight, W1);
    k2_main<<<E_ROWS / TILE_R, 256, SMEM_TOTAL>>>(fea_in1, fea_in2, out);
}

// round 6
// speedup vs baseline: 3.0000x; 1.1578x over previous
#include <cuda_runtime.h>
#include <cuda_fp16.h>
#include <math.h>
#include <stdint.h>

// ---------------------------------------------------------------------------
// EquiConv v5: fp16 2-term compensated HMMA, TILE_R=64, occupancy 2.
//   k0_prepB : W2 -> g_B [18 chunks][128 n][64 k] fp16 (Bh)
//   k1_prep  : H = 1.679*silu((fw@W1)/8)/8 -> g_H ; seg0/1 coefs -> g_C
//   k2_main  : 64-row CTA, 256 thr, warps = (rg 0..3) x (cg 0..1), occ=2.
//              A=[Ah|Al] fp16 (K=128) in SMEM; 18 chunks of 128 cols:
//              cp.async double-buffered B (K=64, shared by Ah/Al blocks),
//              fragment-local contraction, final cg-reduction in SMEM.
// ---------------------------------------------------------------------------

#define E_ROWS 65536
#define TILE_R 64
#define NCHUNK 18
#define ASTR   136                  // fp16 elems per A row (128 + 8)
#define BSTR   72                   // fp16 elems per B row (64 + 8)
#define A_BYTES (TILE_R*ASTR*2)     // 17408
#define BS_OFF  A_BYTES
#define BBUF_B  (128*BSTR*2)        // 18432
#define SMEM_TOTAL (A_BYTES + 2*BBUF_B)   // 54272

__device__ float g_H[E_ROWS * 64];
__device__ float g_C[E_ROWS * 48];
__device__ __align__(16) __half g_B[NCHUNK * 128 * 64];

// ------------------------------ asm helpers --------------------------------
__device__ __forceinline__ uint32_t smem_u32(const void* p) {
    uint32_t a;
    asm("{ .reg .u64 t; cvta.to.shared.u64 t, %1; cvt.u32.u64 %0, t; }" : "=r"(a) : "l"(p));
    return a;
}
#define LDSM4(r, a)                                                          \
    asm volatile("ldmatrix.sync.aligned.m8n8.x4.shared.b16 {%0,%1,%2,%3},[%4];" \
                 : "=r"((r)[0]), "=r"((r)[1]), "=r"((r)[2]), "=r"((r)[3]) : "r"(a))
#define MMA16816(d, a, b)                                                    \
    asm volatile("mma.sync.aligned.m16n8k16.row.col.f32.f16.f16.f32 "        \
                 "{%0,%1,%2,%3},{%4,%5,%6,%7},{%8,%9},{%0,%1,%2,%3};"        \
                 : "+f"((d)[0]), "+f"((d)[1]), "+f"((d)[2]), "+f"((d)[3])    \
                 : "r"((a)[0]), "r"((a)[1]), "r"((a)[2]), "r"((a)[3]),       \
                   "r"((b)[0]), "r"((b)[1]))
#define CP_ASYNC16(d, s) \
    asm volatile("cp.async.cg.shared.global [%0], [%1], 16;" :: "r"(d), "l"(s))
#define CP_COMMIT()   asm volatile("cp.async.commit_group;" ::: "memory")
#define CP_WAIT1()    asm volatile("cp.async.wait_group 1;" ::: "memory")
#define CP_WAIT0()    asm volatile("cp.async.wait_group 0;" ::: "memory")

// stage one B chunk (128 n-rows x 128B) into smem rows of stride 144B
__device__ __forceinline__ void stage_B(int chunk, uint32_t dst, int tid) {
    const char* src = (const char*)(g_B + chunk * 128 * 64);
#pragma unroll
    for (int it = 0; it < 4; it++) {
        int t16 = tid + it * 256;
        int row = t16 >> 3, c = t16 & 7;
        CP_ASYNC16(dst + row * 144 + c * 16, src + row * 128 + c * 16);
    }
}

// ---------------------------------------------------------------------------
__global__ void k0_prepB(const float* __restrict__ W2) {
    int id = blockIdx.x * 256 + threadIdx.x;
    if (id >= 2304 * 64) return;
    int col = id >> 6, kk = id & 63;
    int chunk = col >> 7, n = col & 127;
    g_B[(chunk * 128 + n) * 64 + kk] = __float2half(W2[kk * 2304 + col]);
}

// ---------------------------------------------------------------------------
__global__ void k1_prep(const float* __restrict__ fea_in1,
                        const float* __restrict__ fea_in2,
                        const float* __restrict__ fea_weight,
                        const float* __restrict__ W1)
{
    __shared__ float W1s[64 * 64];
    __shared__ float fws[32 * 64];
    const int t  = threadIdx.x;
    const int r0 = blockIdx.x * 32;

    for (int idx = t; idx < 64 * 64; idx += 256) W1s[idx] = W1[idx];
    for (int idx = t; idx < 32 * 64; idx += 256) fws[idx] = fea_weight[r0 * 64 + idx];
    __syncthreads();

    const int rl = t >> 3, l8 = t & 7, grow = r0 + rl;
    float acc[8];
#pragma unroll
    for (int jj = 0; jj < 8; jj++) acc[jj] = 0.f;
#pragma unroll 8
    for (int k = 0; k < 64; k++) {
        const float fv = fws[rl * 64 + k];
#pragma unroll
        for (int jj = 0; jj < 8; jj++) acc[jj] += fv * W1s[k * 64 + jj * 8 + l8];
    }
#pragma unroll
    for (int jj = 0; jj < 8; jj++) {
        const float z = acc[jj] * 0.125f;
        const float s = z / (1.f + expf(-z));
        g_H[grow * 64 + jj * 8 + l8] = 1.679f * s * 0.125f;   // fold W2's /8
    }

    const float x20  = fea_in2[grow * 4 + 0];
    const float x21a = fea_in2[grow * 4 + 1];
    const float x21b = fea_in2[grow * 4 + 2];
    const float x21c = fea_in2[grow * 4 + 3];
    for (int u = l8; u < 32; u += 8)
        g_C[grow * 48 + u] = 0.125f * x20 * fea_in1[grow * 80 + u];      // pw00
    for (int u = l8; u < 16; u += 8) {
        const float* p = fea_in1 + grow * 80 + 32 + u * 3;
        const float b = p[0] * x21a + p[1] * x21b + p[2] * x21c;
        g_C[grow * 48 + 32 + u] = 0.10206207261596575f * b;              // 1/sqrt(96)
    }
}

// ---------------------------------------------------------------------------
__global__ __launch_bounds__(256, 2)
void k2_main(const float* __restrict__ fea_in1,
             const float* __restrict__ fea_in2,
             float* __restrict__ out)
{
    extern __shared__ __align__(16) char smem[];
    const uint32_t sbase = smem_u32(smem);
    const int tid = threadIdx.x, wid = tid >> 5, lane = tid & 31;
    const int rg = wid >> 1, cg = wid & 1;
    const int r0 = blockIdx.x * TILE_R;

    // ---- build A tile: [64 rows][128 k] fp16 = [Ah|Al], stride 136 ----
    __half* As = (__half*)smem;
    for (int idx = tid; idx < TILE_R * 64; idx += 256) {
        const int r = idx >> 6, j = idx & 63;
        const float h = g_H[(r0 + r) * 64 + j];
        const __half hi = __float2half(h);
        const __half lo = __float2half(h - __half2float(hi));
        As[r * ASTR + j]      = hi;
        As[r * ASTR + 64 + j] = lo;
    }
    stage_B(0, sbase + BS_OFF, tid);            CP_COMMIT();
    stage_B(1, sbase + BS_OFF + BBUF_B, tid);   CP_COMMIT();
    __syncthreads();

    // ldmatrix address groups
    const int gp = lane >> 3, lr = lane & 7;
    const uint32_t aBase = sbase + (uint32_t)(((rg * 16 + 8 * (gp & 1) + lr) * ASTR
                                               + 8 * (gp >> 1)) * 2);
    uint32_t bOff[4];
#pragma unroll
    for (int p = 0; p < 4; p++)
        bOff[p] = (uint32_t)(((cg * 64 + 16 * p + 8 * (gp >> 1) + lr) * BSTR
                              + 8 * (gp & 1)) * 2);

    // persistent per-thread partial accumulators
    float o0[16], sA[8], qA[24];
#pragma unroll
    for (int i = 0; i < 16; i++) o0[i] = 0.f;
#pragma unroll
    for (int i = 0; i < 8; i++) sA[i] = 0.f;
#pragma unroll
    for (int i = 0; i < 24; i++) qA[i] = 0.f;

    const int rowq = lane >> 2;
    const int rbase = r0 + rg * 16 + rowq;     // + rh*8
    const int q2 = (lane & 3) * 2;

#pragma unroll 1
    for (int m = 0; m < NCHUNK; m++) {
        if (m < NCHUNK - 2) { CP_WAIT1(); } else { CP_WAIT0(); }
        __syncthreads();
        const uint32_t sbB = sbase + BS_OFF + (uint32_t)(m & 1) * BBUF_B;

        float acc[8][4];
#pragma unroll
        for (int j = 0; j < 8; j++)
#pragma unroll
            for (int c = 0; c < 4; c++) acc[j][c] = 0.f;

#pragma unroll
        for (int ksb = 0; ksb < 4; ksb++) {
            uint32_t b[8][2];
#pragma unroll
            for (int p = 0; p < 4; p++) {
                uint32_t r[4];
                LDSM4(r, sbB + bOff[p] + ksb * 32);
                b[2 * p][0] = r[0]; b[2 * p][1] = r[1];
                b[2 * p + 1][0] = r[2]; b[2 * p + 1][1] = r[3];
            }
            uint32_t a[4];
            // Ah block
            LDSM4(a, aBase + ksb * 32);
#pragma unroll
            for (int j = 0; j < 8; j++)
                MMA16816(acc[j], a, b[j]);
            // Al block (reuses same B fragments)
            LDSM4(a, aBase + 128 + ksb * 32);
#pragma unroll
            for (int j = 0; j < 8; j++)
                MMA16816(acc[j], a, b[j]);
        }

        // ---- fragment-local contraction (cg-partial) ----
        // warp cols within chunk: cg*64 + j*8 + q2 + {0,1}
        if (m < 12) {
            // seg0/1: u = mbase + cg*2 + (j>>2); w = (j&3)*8 + q2 + {0,1}
            const int ubase = (m < 8 ? m * 4 : 32 + (m - 8) * 4) + cg * 2;
#pragma unroll
            for (int rh = 0; rh < 2; rh++) {
                const int row = rbase + rh * 8;
                const float c0v = g_C[row * 48 + ubase];
                const float c1v = g_C[row * 48 + ubase + 1];
#pragma unroll
                for (int j = 0; j < 8; j++) {
                    const float c = (j < 4) ? c0v : c1v;
                    const int s = (rh * 4 + (j & 3)) * 2;
                    o0[s]     = fmaf(c, acc[j][rh * 2],     o0[s]);
                    o0[s + 1] = fmaf(c, acc[j][rh * 2 + 1], o0[s + 1]);
                }
            }
        } else if (m < 16) {
            // seg2: u = (m-12)*8 + cg*4 + (j>>1); w = (j&1)*8 + q2 + {0,1}
            const int u0 = (m - 12) * 8 + cg * 4;
#pragma unroll
            for (int rh = 0; rh < 2; rh++) {
                const int row = rbase + rh * 8;
                const float* xr = fea_in1 + row * 80 + u0;
#pragma unroll
                for (int j = 0; j < 8; j++) {
                    const float cu = xr[j >> 1];
                    const int s = rh * 4 + (j & 1) * 2;
                    sA[s]     = fmaf(cu, acc[j][rh * 2],     sA[s]);
                    sA[s + 1] = fmaf(cu, acc[j][rh * 2 + 1], sA[s + 1]);
                }
            }
        } else {
            // seg3: u = (m-16)*8 + cg*4 + (j>>1); coef = x1_1[u, 0..2]
            const int u0 = (m - 16) * 8 + cg * 4;
#pragma unroll
            for (int rh = 0; rh < 2; rh++) {
                const int row = rbase + rh * 8;
                const float* xr = fea_in1 + row * 80 + 32 + 3 * u0;
#pragma unroll
                for (int j = 0; j < 8; j++) {
                    const int s = (rh * 4 + (j & 1) * 2) * 3;
#pragma unroll
                    for (int k = 0; k < 3; k++) {
                        const float cu = xr[3 * (j >> 1) + k];
                        qA[s + k]     = fmaf(cu, acc[j][rh * 2],     qA[s + k]);
                        qA[s + 3 + k] = fmaf(cu, acc[j][rh * 2 + 1], qA[s + 3 + k]);
                    }
                }
            }
        }
        __syncthreads();
        if (m + 2 < NCHUNK) {
            stage_B(m + 2, sbase + BS_OFF + (uint32_t)(m & 1) * BBUF_B, tid);
            CP_COMMIT();
        }
    }

    // ---- cross-cg reduction (cg=1 partials -> cg=0), reuse B area ----
    float* red = (float*)(smem + BS_OFF);      // 128 thr * 48 f = 24576 B
    const int half_id = rg * 32 + lane;
    if (cg == 1) {
        float* dst = red + half_id * 48;
#pragma unroll
        for (int i = 0; i < 16; i++) dst[i] = o0[i];
#pragma unroll
        for (int i = 0; i < 8; i++) dst[16 + i] = sA[i];
#pragma unroll
        for (int i = 0; i < 24; i++) dst[24 + i] = qA[i];
    }
    __syncthreads();
    if (cg == 0) {
        const float* src = red + half_id * 48;
#pragma unroll
        for (int i = 0; i < 16; i++) o0[i] += src[i];
#pragma unroll
        for (int i = 0; i < 8; i++) sA[i] += src[16 + i];
#pragma unroll
        for (int i = 0; i < 24; i++) qA[i] += src[24 + i];

        // ---- epilogue ----
        const float c011 = 0.125f;                 // pw011/sqrt(3)
        const float c101 = 0.17677669529663687f;   // pw101/sqrt(3)
#pragma unroll
        for (int rh = 0; rh < 2; rh++) {
            const int row = rbase + rh * 8;
            float* orow = out + row * 80;
            const int s = rh * 4;
#pragma unroll
            for (int jm = 0; jm < 4; jm++) {           // out0 cols (j&3)=jm
                orow[8 * jm + q2]     = o0[(s + jm) * 2];
                orow[8 * jm + q2 + 1] = o0[(s + jm) * 2 + 1];
            }
            const float x20  = fea_in2[row * 4 + 0];
            const float x21a = fea_in2[row * 4 + 1];
            const float x21b = fea_in2[row * 4 + 2];
            const float x21c = fea_in2[row * 4 + 3];
#pragma unroll
            for (int slot = 0; slot < 4; slot++) {     // w = (slot>>1)*8 + q2 + (slot&1)
                const int w = 8 * (slot >> 1) + q2 + (slot & 1);
                const float sv = sA[s + slot];
                orow[32 + 3 * w + 0] = c011 * x21a * sv + c101 * x20 * qA[(s + slot) * 3 + 0];
                orow[32 + 3 * w + 1] = c011 * x21b * sv + c101 * x20 * qA[(s + slot) * 3 + 1];
                orow[32 + 3 * w + 2] = c011 * x21c * sv + c101 * x20 * qA[(s + slot) * 3 + 2];
            }
        }
    }
}

// ---------------------------------------------------------------------------
extern "C" void kernel_launch(void* const* d_in, const int* in_sizes, int n_in,
                              void* d_out, int out_size)
{
    const float* fea_in1    = (const float*)d_in[0];
    const float* fea_in2    = (const float*)d_in[1];
    const float* fea_weight = (const float*)d_in[2];
    const float* W1         = (const float*)d_in[3];
    const float* W2         = (const float*)d_in[4];
    float* out = (float*)d_out;

    cudaFuncSetAttribute(k2_main, cudaFuncAttributeMaxDynamicSharedMemorySize, SMEM_TOTAL);

    k0_prepB<<<576, 256>>>(W2);
    k1_prep<<<E_ROWS / 32, 256>>>(fea_in1, fea_in2, fea_weight, W1);
    k2_main<<<E_ROWS / TILE_R, 256, SMEM_TOTAL>>>(fea_in1, fea_in2, out);
}

// round 7
// speedup vs baseline: 3.2388x; 1.0796x over previous
#include <cuda_runtime.h>
#include <cuda_fp16.h>
#include <math.h>
#include <stdint.h>

// ---------------------------------------------------------------------------
// EquiConv v6: single-term fp16 HMMA (K=64), TILE_R=64, occupancy 2.
//   k0_prepB : W2 -> g_B [18 chunks][128 n][64 k] fp16
//   k1_prep  : H = 1.679*silu((fw@W1)/8)/8 -> g_H ; seg0/1 coefs -> g_C
//   k2_main  : 64-row CTA, 256 thr, warps = (rg 0..3) x (cg 0..1), occ=2.
//              A fp16 (K=64) in SMEM; 18 chunks of 128 cols:
//              cp.async double-buffered B, fragment-local contraction,
//              final cg-reduction in SMEM.
// ---------------------------------------------------------------------------

#define E_ROWS 65536
#define TILE_R 64
#define NCHUNK 18
#define ASTR   72                   // fp16 elems per A row (64 + 8)
#define BSTR   72                   // fp16 elems per B row (64 + 8)
#define A_BYTES (TILE_R*ASTR*2)     // 9216
#define BS_OFF  A_BYTES
#define BBUF_B  (128*BSTR*2)        // 18432
#define SMEM_TOTAL (A_BYTES + 2*BBUF_B)   // 46080

__device__ float g_H[E_ROWS * 64];
__device__ float g_C[E_ROWS * 48];
__device__ __align__(16) __half g_B[NCHUNK * 128 * 64];

// ------------------------------ asm helpers --------------------------------
__device__ __forceinline__ uint32_t smem_u32(const void* p) {
    uint32_t a;
    asm("{ .reg .u64 t; cvta.to.shared.u64 t, %1; cvt.u32.u64 %0, t; }" : "=r"(a) : "l"(p));
    return a;
}
#define LDSM4(r, a)                                                          \
    asm volatile("ldmatrix.sync.aligned.m8n8.x4.shared.b16 {%0,%1,%2,%3},[%4];" \
                 : "=r"((r)[0]), "=r"((r)[1]), "=r"((r)[2]), "=r"((r)[3]) : "r"(a))
#define MMA16816(d, a, b)                                                    \
    asm volatile("mma.sync.aligned.m16n8k16.row.col.f32.f16.f16.f32 "        \
                 "{%0,%1,%2,%3},{%4,%5,%6,%7},{%8,%9},{%0,%1,%2,%3};"        \
                 : "+f"((d)[0]), "+f"((d)[1]), "+f"((d)[2]), "+f"((d)[3])    \
                 : "r"((a)[0]), "r"((a)[1]), "r"((a)[2]), "r"((a)[3]),       \
                   "r"((b)[0]), "r"((b)[1]))
#define CP_ASYNC16(d, s) \
    asm volatile("cp.async.cg.shared.global [%0], [%1], 16;" :: "r"(d), "l"(s))
#define CP_COMMIT()   asm volatile("cp.async.commit_group;" ::: "memory")
#define CP_WAIT1()    asm volatile("cp.async.wait_group 1;" ::: "memory")
#define CP_WAIT0()    asm volatile("cp.async.wait_group 0;" ::: "memory")

// stage one B chunk (128 n-rows x 128B) into smem rows of stride 144B
__device__ __forceinline__ void stage_B(int chunk, uint32_t dst, int tid) {
    const char* src = (const char*)(g_B + chunk * 128 * 64);
#pragma unroll
    for (int it = 0; it < 4; it++) {
        int t16 = tid + it * 256;
        int row = t16 >> 3, c = t16 & 7;
        CP_ASYNC16(dst + row * 144 + c * 16, src + row * 128 + c * 16);
    }
}

// ---------------------------------------------------------------------------
__global__ void k0_prepB(const float* __restrict__ W2) {
    int id = blockIdx.x * 256 + threadIdx.x;
    if (id >= 2304 * 64) return;
    int col = id >> 6, kk = id & 63;
    int chunk = col >> 7, n = col & 127;
    g_B[(chunk * 128 + n) * 64 + kk] = __float2half(W2[kk * 2304 + col]);
}

// ---------------------------------------------------------------------------
__global__ void k1_prep(const float* __restrict__ fea_in1,
                        const float* __restrict__ fea_in2,
                        const float* __restrict__ fea_weight,
                        const float* __restrict__ W1)
{
    __shared__ float W1s[64 * 64];
    __shared__ float fws[32 * 64];
    const int t  = threadIdx.x;
    const int r0 = blockIdx.x * 32;

    for (int idx = t; idx < 64 * 64; idx += 256) W1s[idx] = W1[idx];
    for (int idx = t; idx < 32 * 64; idx += 256) fws[idx] = fea_weight[r0 * 64 + idx];
    __syncthreads();

    const int rl = t >> 3, l8 = t & 7, grow = r0 + rl;
    float acc[8];
#pragma unroll
    for (int jj = 0; jj < 8; jj++) acc[jj] = 0.f;
#pragma unroll 8
    for (int k = 0; k < 64; k++) {
        const float fv = fws[rl * 64 + k];
#pragma unroll
        for (int jj = 0; jj < 8; jj++) acc[jj] += fv * W1s[k * 64 + jj * 8 + l8];
    }
#pragma unroll
    for (int jj = 0; jj < 8; jj++) {
        const float z = acc[jj] * 0.125f;
        const float s = z / (1.f + expf(-z));
        g_H[grow * 64 + jj * 8 + l8] = 1.679f * s * 0.125f;   // fold W2's /8
    }

    const float x20  = fea_in2[grow * 4 + 0];
    const float x21a = fea_in2[grow * 4 + 1];
    const float x21b = fea_in2[grow * 4 + 2];
    const float x21c = fea_in2[grow * 4 + 3];
    for (int u = l8; u < 32; u += 8)
        g_C[grow * 48 + u] = 0.125f * x20 * fea_in1[grow * 80 + u];      // pw00
    for (int u = l8; u < 16; u += 8) {
        const float* p = fea_in1 + grow * 80 + 32 + u * 3;
        const float b = p[0] * x21a + p[1] * x21b + p[2] * x21c;
        g_C[grow * 48 + 32 + u] = 0.10206207261596575f * b;              // 1/sqrt(96)
    }
}

// ---------------------------------------------------------------------------
__global__ __launch_bounds__(256, 2)
void k2_main(const float* __restrict__ fea_in1,
             const float* __restrict__ fea_in2,
             float* __restrict__ out)
{
    extern __shared__ __align__(16) char smem[];
    const uint32_t sbase = smem_u32(smem);
    const int tid = threadIdx.x, wid = tid >> 5, lane = tid & 31;
    const int rg = wid >> 1, cg = wid & 1;
    const int r0 = blockIdx.x * TILE_R;

    // ---- build A tile: [64 rows][64 k] fp16, stride 72 ----
    __half* As = (__half*)smem;
    for (int idx = tid; idx < TILE_R * 64; idx += 256) {
        const int r = idx >> 6, j = idx & 63;
        As[r * ASTR + j] = __float2half(g_H[(r0 + r) * 64 + j]);
    }
    stage_B(0, sbase + BS_OFF, tid);            CP_COMMIT();
    stage_B(1, sbase + BS_OFF + BBUF_B, tid);   CP_COMMIT();
    __syncthreads();

    // ldmatrix address groups
    const int gp = lane >> 3, lr = lane & 7;
    const uint32_t aBase = sbase + (uint32_t)(((rg * 16 + 8 * (gp & 1) + lr) * ASTR
                                               + 8 * (gp >> 1)) * 2);
    uint32_t bOff[4];
#pragma unroll
    for (int p = 0; p < 4; p++)
        bOff[p] = (uint32_t)(((cg * 64 + 16 * p + 8 * (gp >> 1) + lr) * BSTR
                              + 8 * (gp & 1)) * 2);

    // persistent per-thread partial accumulators
    float o0[16], sA[8], qA[24];
#pragma unroll
    for (int i = 0; i < 16; i++) o0[i] = 0.f;
#pragma unroll
    for (int i = 0; i < 8; i++) sA[i] = 0.f;
#pragma unroll
    for (int i = 0; i < 24; i++) qA[i] = 0.f;

    const int rowq = lane >> 2;
    const int rbase = r0 + rg * 16 + rowq;     // + rh*8
    const int q2 = (lane & 3) * 2;

#pragma unroll 1
    for (int m = 0; m < NCHUNK; m++) {
        if (m < NCHUNK - 2) { CP_WAIT1(); } else { CP_WAIT0(); }
        __syncthreads();
        const uint32_t sbB = sbase + BS_OFF + (uint32_t)(m & 1) * BBUF_B;

        float acc[8][4];
#pragma unroll
        for (int j = 0; j < 8; j++)
#pragma unroll
            for (int c = 0; c < 4; c++) acc[j][c] = 0.f;

#pragma unroll
        for (int ksb = 0; ksb < 4; ksb++) {
            uint32_t b[8][2];
#pragma unroll
            for (int p = 0; p < 4; p++) {
                uint32_t r[4];
                LDSM4(r, sbB + bOff[p] + ksb * 32);
                b[2 * p][0] = r[0]; b[2 * p][1] = r[1];
                b[2 * p + 1][0] = r[2]; b[2 * p + 1][1] = r[3];
            }
            uint32_t a[4];
            LDSM4(a, aBase + ksb * 32);
#pragma unroll
            for (int j = 0; j < 8; j++)
                MMA16816(acc[j], a, b[j]);
        }

        // ---- fragment-local contraction (cg-partial) ----
        // warp cols within chunk: cg*64 + j*8 + q2 + {0,1}
        if (m < 12) {
            // seg0/1: u = mbase + cg*2 + (j>>2); w = (j&3)*8 + q2 + {0,1}
            const int ubase = (m < 8 ? m * 4 : 32 + (m - 8) * 4) + cg * 2;
#pragma unroll
            for (int rh = 0; rh < 2; rh++) {
                const int row = rbase + rh * 8;
                const float c0v = g_C[row * 48 + ubase];
                const float c1v = g_C[row * 48 + ubase + 1];
#pragma unroll
                for (int j = 0; j < 8; j++) {
                    const float c = (j < 4) ? c0v : c1v;
                    const int s = (rh * 4 + (j & 3)) * 2;
                    o0[s]     = fmaf(c, acc[j][rh * 2],     o0[s]);
                    o0[s + 1] = fmaf(c, acc[j][rh * 2 + 1], o0[s + 1]);
                }
            }
        } else if (m < 16) {
            // seg2: u = (m-12)*8 + cg*4 + (j>>1); w = (j&1)*8 + q2 + {0,1}
            const int u0 = (m - 12) * 8 + cg * 4;
#pragma unroll
            for (int rh = 0; rh < 2; rh++) {
                const int row = rbase + rh * 8;
                const float* xr = fea_in1 + row * 80 + u0;
#pragma unroll
                for (int j = 0; j < 8; j++) {
                    const float cu = xr[j >> 1];
                    const int s = rh * 4 + (j & 1) * 2;
                    sA[s]     = fmaf(cu, acc[j][rh * 2],     sA[s]);
                    sA[s + 1] = fmaf(cu, acc[j][rh * 2 + 1], sA[s + 1]);
                }
            }
        } else {
            // seg3: u = (m-16)*8 + cg*4 + (j>>1); coef = x1_1[u, 0..2]
            const int u0 = (m - 16) * 8 + cg * 4;
#pragma unroll
            for (int rh = 0; rh < 2; rh++) {
                const int row = rbase + rh * 8;
                const float* xr = fea_in1 + row * 80 + 32 + 3 * u0;
#pragma unroll
                for (int j = 0; j < 8; j++) {
                    const int s = (rh * 4 + (j & 1) * 2) * 3;
#pragma unroll
                    for (int k = 0; k < 3; k++) {
                        const float cu = xr[3 * (j >> 1) + k];
                        qA[s + k]     = fmaf(cu, acc[j][rh * 2],     qA[s + k]);
                        qA[s + 3 + k] = fmaf(cu, acc[j][rh * 2 + 1], qA[s + 3 + k]);
                    }
                }
            }
        }
        __syncthreads();
        if (m + 2 < NCHUNK) {
            stage_B(m + 2, sbase + BS_OFF + (uint32_t)(m & 1) * BBUF_B, tid);
            CP_COMMIT();
        }
    }

    // ---- cross-cg reduction (cg=1 partials -> cg=0), reuse B area ----
    float* red = (float*)(smem + BS_OFF);      // 128 thr * 48 f = 24576 B
    const int half_id = rg * 32 + lane;
    if (cg == 1) {
        float* dst = red + half_id * 48;
#pragma unroll
        for (int i = 0; i < 16; i++) dst[i] = o0[i];
#pragma unroll
        for (int i = 0; i < 8; i++) dst[16 + i] = sA[i];
#pragma unroll
        for (int i = 0; i < 24; i++) dst[24 + i] = qA[i];
    }
    __syncthreads();
    if (cg == 0) {
        const float* src = red + half_id * 48;
#pragma unroll
        for (int i = 0; i < 16; i++) o0[i] += src[i];
#pragma unroll
        for (int i = 0; i < 8; i++) sA[i] += src[16 + i];
#pragma unroll
        for (int i = 0; i < 24; i++) qA[i] += src[24 + i];

        // ---- epilogue ----
        const float c011 = 0.125f;                 // pw011/sqrt(3)
        const float c101 = 0.17677669529663687f;   // pw101/sqrt(3)
#pragma unroll
        for (int rh = 0; rh < 2; rh++) {
            const int row = rbase + rh * 8;
            float* orow = out + row * 80;
            const int s = rh * 4;
#pragma unroll
            for (int jm = 0; jm < 4; jm++) {           // out0 cols (j&3)=jm
                orow[8 * jm + q2]     = o0[(s + jm) * 2];
                orow[8 * jm + q2 + 1] = o0[(s + jm) * 2 + 1];
            }
            const float x20  = fea_in2[row * 4 + 0];
            const float x21a = fea_in2[row * 4 + 1];
            const float x21b = fea_in2[row * 4 + 2];
            const float x21c = fea_in2[row * 4 + 3];
#pragma unroll
            for (int slot = 0; slot < 4; slot++) {     // w = (slot>>1)*8 + q2 + (slot&1)
                const int w = 8 * (slot >> 1) + q2 + (slot & 1);
                const float sv = sA[s + slot];
                orow[32 + 3 * w + 0] = c011 * x21a * sv + c101 * x20 * qA[(s + slot) * 3 + 0];
                orow[32 + 3 * w + 1] = c011 * x21b * sv + c101 * x20 * qA[(s + slot) * 3 + 1];
                orow[32 + 3 * w + 2] = c011 * x21c * sv + c101 * x20 * qA[(s + slot) * 3 + 2];
            }
        }
    }
}

// ---------------------------------------------------------------------------
extern "C" void kernel_launch(void* const* d_in, const int* in_sizes, int n_in,
                              void* d_out, int out_size)
{
    const float* fea_in1    = (const float*)d_in[0];
    const float* fea_in2    = (const float*)d_in[1];
    const float* fea_weight = (const float*)d_in[2];
    const float* W1         = (const float*)d_in[3];
    const float* W2         = (const float*)d_in[4];
    float* out = (float*)d_out;

    cudaFuncSetAttribute(k2_main, cudaFuncAttributeMaxDynamicSharedMemorySize, SMEM_TOTAL);

    k0_prepB<<<576, 256>>>(W2);
    k1_prep<<<E_ROWS / 32, 256>>>(fea_in1, fea_in2, fea_weight, W1);
    k2_main<<<E_ROWS / TILE_R, 256, SMEM_TOTAL>>>(fea_in1, fea_in2, out);
}

// round 8
// speedup vs baseline: 3.5333x; 1.0909x over previous
#include <cuda_runtime.h>
#include <cuda_fp16.h>
#include <math.h>
#include <stdint.h>

// ---------------------------------------------------------------------------
// EquiConv v7: fp16 HMMA (K=64), chunk-paired mainloop, hoisted A fragments,
//              merged prep kernel (2 launches per call).
//   k01_prep : W2 -> g_B fp16 chunks  +  H/silu -> g_H, seg0/1 coefs -> g_C
//   k2_main  : 64-row CTA, 256 thr, warps = (rg 0..3) x (cg 0..1), occ=2.
//              9 pairs of 128-col chunks, cp.async double-buffered pair
//              buffers, fragment-local contraction, cg-reduction in SMEM.
// ---------------------------------------------------------------------------

#define E_ROWS 65536
#define TILE_R 64
#define NCHUNK 18
#define NPAIR  9
#define ASTR   72                   // fp16 elems per A row (64 + 8)
#define BSTR   72                   // fp16 elems per B row (64 + 8)
#define A_BYTES (TILE_R*ASTR*2)     // 9216
#define BS_OFF  A_BYTES
#define BBUF_B  (128*BSTR*2)        // 18432 (one chunk)
#define PAIR_B  (2*BBUF_B)          // 36864 (one pair buffer)
#define SMEM_TOTAL (A_BYTES + 2*PAIR_B)   // 82944

__device__ float g_H[E_ROWS * 64];
__device__ float g_C[E_ROWS * 48];
__device__ __align__(16) __half g_B[NCHUNK * 128 * 64];

// ------------------------------ asm helpers --------------------------------
__device__ __forceinline__ uint32_t smem_u32(const void* p) {
    uint32_t a;
    asm("{ .reg .u64 t; cvta.to.shared.u64 t, %1; cvt.u32.u64 %0, t; }" : "=r"(a) : "l"(p));
    return a;
}
#define LDSM4(r, a)                                                          \
    asm volatile("ldmatrix.sync.aligned.m8n8.x4.shared.b16 {%0,%1,%2,%3},[%4];" \
                 : "=r"((r)[0]), "=r"((r)[1]), "=r"((r)[2]), "=r"((r)[3]) : "r"(a))
#define MMA16816(d, a, b)                                                    \
    asm volatile("mma.sync.aligned.m16n8k16.row.col.f32.f16.f16.f32 "        \
                 "{%0,%1,%2,%3},{%4,%5,%6,%7},{%8,%9},{%0,%1,%2,%3};"        \
                 : "+f"((d)[0]), "+f"((d)[1]), "+f"((d)[2]), "+f"((d)[3])    \
                 : "r"((a)[0]), "r"((a)[1]), "r"((a)[2]), "r"((a)[3]),       \
                   "r"((b)[0]), "r"((b)[1]))
#define CP_ASYNC16(d, s) \
    asm volatile("cp.async.cg.shared.global [%0], [%1], 16;" :: "r"(d), "l"(s))
#define CP_COMMIT()   asm volatile("cp.async.commit_group;" ::: "memory")
#define CP_WAIT1()    asm volatile("cp.async.wait_group 1;" ::: "memory")
#define CP_WAIT0()    asm volatile("cp.async.wait_group 0;" ::: "memory")

// stage one pair (2 chunks, 256 rows x 128B) into pair buffer (rows stride 144B)
__device__ __forceinline__ void stage_pair(int pair, uint32_t dst, int tid) {
    const char* src = (const char*)(g_B + pair * 2 * 128 * 64);
#pragma unroll
    for (int it = 0; it < 8; it++) {
        int t16 = tid + it * 256;          // 0..2047
        int row = t16 >> 3, c = t16 & 7;   // row 0..255
        CP_ASYNC16(dst + (uint32_t)(row >> 7) * BBUF_B + (row & 127) * 144 + c * 16,
                   src + row * 128 + c * 16);
    }
}

// ---------------------------------------------------------------------------
__global__ void k01_prep(const float* __restrict__ fea_in1,
                         const float* __restrict__ fea_in2,
                         const float* __restrict__ fea_weight,
                         const float* __restrict__ W1,
                         const float* __restrict__ W2)
{
    __shared__ float W1s[64 * 64];
    __shared__ float fws[32 * 64];
    const int t  = threadIdx.x;
    const int r0 = blockIdx.x * 32;

    // ---- k0 part: W2 -> g_B fp16, chunked layout (blocks < 576) ----
    if (blockIdx.x < 576) {
        int id = blockIdx.x * 256 + t;     // covers 2304*64 exactly
        int col = id >> 6, kk = id & 63;
        int chunk = col >> 7, n = col & 127;
        g_B[(chunk * 128 + n) * 64 + kk] = __float2half(W2[kk * 2304 + col]);
    }

    // ---- k1 part ----
    for (int idx = t; idx < 64 * 64; idx += 256) W1s[idx] = W1[idx];
    for (int idx = t; idx < 32 * 64; idx += 256) fws[idx] = fea_weight[r0 * 64 + idx];
    __syncthreads();

    const int rl = t >> 3, l8 = t & 7, grow = r0 + rl;
    float acc[8];
#pragma unroll
    for (int jj = 0; jj < 8; jj++) acc[jj] = 0.f;
#pragma unroll 8
    for (int k = 0; k < 64; k++) {
        const float fv = fws[rl * 64 + k];
#pragma unroll
        for (int jj = 0; jj < 8; jj++) acc[jj] += fv * W1s[k * 64 + jj * 8 + l8];
    }
#pragma unroll
    for (int jj = 0; jj < 8; jj++) {
        const float z = acc[jj] * 0.125f;
        const float s = z / (1.f + expf(-z));
        g_H[grow * 64 + jj * 8 + l8] = 1.679f * s * 0.125f;   // fold W2's /8
    }

    const float x20  = fea_in2[grow * 4 + 0];
    const float x21a = fea_in2[grow * 4 + 1];
    const float x21b = fea_in2[grow * 4 + 2];
    const float x21c = fea_in2[grow * 4 + 3];
    for (int u = l8; u < 32; u += 8)
        g_C[grow * 48 + u] = 0.125f * x20 * fea_in1[grow * 80 + u];      // pw00
    for (int u = l8; u < 16; u += 8) {
        const float* p = fea_in1 + grow * 80 + 32 + u * 3;
        const float b = p[0] * x21a + p[1] * x21b + p[2] * x21c;
        g_C[grow * 48 + 32 + u] = 0.10206207261596575f * b;              // 1/sqrt(96)
    }
}

// ---------------------------------------------------------------------------
// one chunk of HMMA into acc (A fragments hoisted by caller)
__device__ __forceinline__ void mma_chunk(float acc[8][4], uint32_t sbB,
                                          const uint32_t afrag[4][4],
                                          const uint32_t bOff[4])
{
#pragma unroll
    for (int j = 0; j < 8; j++)
#pragma unroll
        for (int c = 0; c < 4; c++) acc[j][c] = 0.f;
#pragma unroll
    for (int ksb = 0; ksb < 4; ksb++) {
        uint32_t b[8][2];
#pragma unroll
        for (int p = 0; p < 4; p++) {
            uint32_t r[4];
            LDSM4(r, sbB + bOff[p] + ksb * 32);
            b[2 * p][0] = r[0]; b[2 * p][1] = r[1];
            b[2 * p + 1][0] = r[2]; b[2 * p + 1][1] = r[3];
        }
#pragma unroll
        for (int j = 0; j < 8; j++)
            MMA16816(acc[j], afrag[ksb], b[j]);
    }
}

// contraction of one chunk's acc into persistent accumulators
__device__ __forceinline__ void contract_chunk(
    int m, const float acc[8][4], float* o0, float* sA, float* qA,
    int rbase, int cg, const float* __restrict__ fea_in1)
{
    if (m < 12) {
        const int ubase = (m < 8 ? m * 4 : 32 + (m - 8) * 4) + cg * 2;
#pragma unroll
        for (int rh = 0; rh < 2; rh++) {
            const int row = rbase + rh * 8;
            const float c0v = g_C[row * 48 + ubase];
            const float c1v = g_C[row * 48 + ubase + 1];
#pragma unroll
            for (int j = 0; j < 8; j++) {
                const float c = (j < 4) ? c0v : c1v;
                const int s = (rh * 4 + (j & 3)) * 2;
                o0[s]     = fmaf(c, acc[j][rh * 2],     o0[s]);
                o0[s + 1] = fmaf(c, acc[j][rh * 2 + 1], o0[s + 1]);
            }
        }
    } else if (m < 16) {
        const int u0 = (m - 12) * 8 + cg * 4;
#pragma unroll
        for (int rh = 0; rh < 2; rh++) {
            const int row = rbase + rh * 8;
            const float* xr = fea_in1 + row * 80 + u0;
#pragma unroll
            for (int j = 0; j < 8; j++) {
                const float cu = xr[j >> 1];
                const int s = rh * 4 + (j & 1) * 2;
                sA[s]     = fmaf(cu, acc[j][rh * 2],     sA[s]);
                sA[s + 1] = fmaf(cu, acc[j][rh * 2 + 1], sA[s + 1]);
            }
        }
    } else {
        const int u0 = (m - 16) * 8 + cg * 4;
#pragma unroll
        for (int rh = 0; rh < 2; rh++) {
            const int row = rbase + rh * 8;
            const float* xr = fea_in1 + row * 80 + 32 + 3 * u0;
#pragma unroll
            for (int j = 0; j < 8; j++) {
                const int s = (rh * 4 + (j & 1) * 2) * 3;
#pragma unroll
                for (int k = 0; k < 3; k++) {
                    const float cu = xr[3 * (j >> 1) + k];
                    qA[s + k]     = fmaf(cu, acc[j][rh * 2],     qA[s + k]);
                    qA[s + 3 + k] = fmaf(cu, acc[j][rh * 2 + 1], qA[s + 3 + k]);
                }
            }
        }
    }
}

// ---------------------------------------------------------------------------
__global__ __launch_bounds__(256, 2)
void k2_main(const float* __restrict__ fea_in1,
             const float* __restrict__ fea_in2,
             float* __restrict__ out)
{
    extern __shared__ __align__(16) char smem[];
    const uint32_t sbase = smem_u32(smem);
    const int tid = threadIdx.x, wid = tid >> 5, lane = tid & 31;
    const int rg = wid >> 1, cg = wid & 1;
    const int r0 = blockIdx.x * TILE_R;

    // ---- build A tile: [64 rows][64 k] fp16, stride 72 ----
    __half* As = (__half*)smem;
    for (int idx = tid; idx < TILE_R * 64; idx += 256) {
        const int r = idx >> 6, j = idx & 63;
        As[r * ASTR + j] = __float2half(g_H[(r0 + r) * 64 + j]);
    }
    stage_pair(0, sbase + BS_OFF, tid);            CP_COMMIT();
    stage_pair(1, sbase + BS_OFF + PAIR_B, tid);   CP_COMMIT();
    __syncthreads();

    // ldmatrix address groups
    const int gp = lane >> 3, lr = lane & 7;
    const uint32_t aBase = sbase + (uint32_t)(((rg * 16 + 8 * (gp & 1) + lr) * ASTR
                                               + 8 * (gp >> 1)) * 2);
    uint32_t bOff[4];
#pragma unroll
    for (int p = 0; p < 4; p++)
        bOff[p] = (uint32_t)(((cg * 64 + 16 * p + 8 * (gp >> 1) + lr) * BSTR
                              + 8 * (gp & 1)) * 2);

    // hoist A fragments (chunk-invariant)
    uint32_t afrag[4][4];
#pragma unroll
    for (int ksb = 0; ksb < 4; ksb++)
        LDSM4(afrag[ksb], aBase + ksb * 32);

    // persistent per-thread partial accumulators
    float o0[16], sA[8], qA[24];
#pragma unroll
    for (int i = 0; i < 16; i++) o0[i] = 0.f;
#pragma unroll
    for (int i = 0; i < 8; i++) sA[i] = 0.f;
#pragma unroll
    for (int i = 0; i < 24; i++) qA[i] = 0.f;

    const int rowq = lane >> 2;
    const int rbase = r0 + rg * 16 + rowq;     // + rh*8
    const int q2 = (lane & 3) * 2;

    float acc[8][4];

#pragma unroll 1
    for (int p = 0; p < NPAIR; p++) {
        if (p < NPAIR - 1) { CP_WAIT1(); } else { CP_WAIT0(); }
        __syncthreads();
        const uint32_t pbuf = sbase + BS_OFF + (uint32_t)(p & 1) * PAIR_B;

        // chunk 2p
        mma_chunk(acc, pbuf, afrag, bOff);
        contract_chunk(2 * p, acc, o0, sA, qA, rbase, cg, fea_in1);
        // chunk 2p+1
        mma_chunk(acc, pbuf + BBUF_B, afrag, bOff);
        __syncthreads();                      // all B reads of this pair done
        if (p + 2 < NPAIR) {                  // refill this pair buffer
            stage_pair(p + 2, pbuf, tid);
            CP_COMMIT();
        }
        contract_chunk(2 * p + 1, acc, o0, sA, qA, rbase, cg, fea_in1);
    }

    // ---- cross-cg reduction (cg=1 partials -> cg=0), reuse B area ----
    float* red = (float*)(smem + BS_OFF);      // 128 thr * 48 f = 24576 B
    const int half_id = rg * 32 + lane;
    if (cg == 1) {
        float* dst = red + half_id * 48;
#pragma unroll
        for (int i = 0; i < 16; i++) dst[i] = o0[i];
#pragma unroll
        for (int i = 0; i < 8; i++) dst[16 + i] = sA[i];
#pragma unroll
        for (int i = 0; i < 24; i++) dst[24 + i] = qA[i];
    }
    __syncthreads();
    if (cg == 0) {
        const float* src = red + half_id * 48;
#pragma unroll
        for (int i = 0; i < 16; i++) o0[i] += src[i];
#pragma unroll
        for (int i = 0; i < 8; i++) sA[i] += src[16 + i];
#pragma unroll
        for (int i = 0; i < 24; i++) qA[i] += src[24 + i];

        // ---- epilogue ----
        const float c011 = 0.125f;                 // pw011/sqrt(3)
        const float c101 = 0.17677669529663687f;   // pw101/sqrt(3)
#pragma unroll
        for (int rh = 0; rh < 2; rh++) {
            const int row = rbase + rh * 8;
            float* orow = out + row * 80;
            const int s = rh * 4;
#pragma unroll
            for (int jm = 0; jm < 4; jm++) {
                orow[8 * jm + q2]     = o0[(s + jm) * 2];
                orow[8 * jm + q2 + 1] = o0[(s + jm) * 2 + 1];
            }
            const float x20  = fea_in2[row * 4 + 0];
            const float x21a = fea_in2[row * 4 + 1];
            const float x21b = fea_in2[row * 4 + 2];
            const float x21c = fea_in2[row * 4 + 3];
#pragma unroll
            for (int slot = 0; slot < 4; slot++) {
                const int w = 8 * (slot >> 1) + q2 + (slot & 1);
                const float sv = sA[s + slot];
                orow[32 + 3 * w + 0] = c011 * x21a * sv + c101 * x20 * qA[(s + slot) * 3 + 0];
                orow[32 + 3 * w + 1] = c011 * x21b * sv + c101 * x20 * qA[(s + slot) * 3 + 1];
                orow[32 + 3 * w + 2] = c011 * x21c * sv + c101 * x20 * qA[(s + slot) * 3 + 2];
            }
        }
    }
}

// ---------------------------------------------------------------------------
extern "C" void kernel_launch(void* const* d_in, const int* in_sizes, int n_in,
                              void* d_out, int out_size)
{
    const float* fea_in1    = (const float*)d_in[0];
    const float* fea_in2    = (const float*)d_in[1];
    const float* fea_weight = (const float*)d_in[2];
    const float* W1         = (const float*)d_in[3];
    const float* W2         = (const float*)d_in[4];
    float* out = (float*)d_out;

    cudaFuncSetAttribute(k2_main, cudaFuncAttributeMaxDynamicSharedMemorySize, SMEM_TOTAL);

    k01_prep<<<E_ROWS / 32, 256>>>(fea_in1, fea_in2, fea_weight, W1, W2);
    k2_main<<<E_ROWS / TILE_R, 256, SMEM_TOTAL>>>(fea_in1, fea_in2, out);
}